// round 8
// baseline (speedup 1.0000x reference)
#include <cuda_runtime.h>
#include <math.h>
#include <stdint.h>

#define DIM     2048
#define NE      128
#define KSEL    4
#define BM      128     // tokens per CTA
#define KC      32      // K elems per chunk (4 k-steps of 8)
#define NCHUNK  (DIM/KC)
#define THREADS 1024
#define LST     129     // logits smem stride
#define ABLK    33      // padded float4 slots per (rowgroup, kstep) block

#define ABUF_BYTES (16 * 4 * ABLK * 16)   // 33792
#define BBUF_BYTES (2048 * 16)            // 32768
#define BOFF       (2 * ABUF_BYTES)       // 67584
#define SOFF       (BOFF + 2 * BBUF_BYTES)            // 133120
#define SMEM_TOTAL (SOFF + 16 * THREADS * 4)          // 198656

// Chunk-major fragment W (hi/lo split): g_Wfrag[((chunk*16 + n8)*4 + ksl)*32 + lane]
//   = {Whi[n8*8+tr][k], Whi[..][k+4], Wlo[..][k], Wlo[..][k+4]},
//   lane = tr*4+tc, k = chunk*32 + ksl*8 + tc
__device__ float4 g_Wfrag[NCHUNK * 2048];   // 2 MB

__device__ __forceinline__ uint32_t smem_u32(const void* p) {
    uint32_t a;
    asm("{ .reg .u64 t; cvta.to.shared.u64 t, %1; cvt.u32.u64 %0, t; }" : "=r"(a) : "l"(p));
    return a;
}
__device__ __forceinline__ void cp_async16(uint32_t dst, const void* src) {
    asm volatile("cp.async.cg.shared.global [%0], [%1], 16;" :: "r"(dst), "l"(src) : "memory");
}
#define CP_COMMIT() asm volatile("cp.async.commit_group;" ::: "memory")
#define CP_WAIT0()  asm volatile("cp.async.wait_group 0;" ::: "memory")

// Split fp32 into tf32 hi + tf32 lo (x = hi + lo + O(2^-33 x))
__device__ __forceinline__ void split_tf32(float v, float& hi, float& lo) {
    unsigned h, l;
    asm("cvt.rna.tf32.f32 %0, %1;" : "=r"(h) : "f"(v));
    hi = __uint_as_float(h);
    float r = v - hi;
    asm("cvt.rna.tf32.f32 %0, %1;" : "=r"(l) : "f"(r));
    lo = __uint_as_float(l);
}

__device__ __forceinline__ void mma_tf32(float c[4],
                                         unsigned a0, unsigned a1, unsigned a2, unsigned a3,
                                         unsigned b0, unsigned b1) {
    asm volatile(
        "mma.sync.aligned.m16n8k8.row.col.f32.tf32.tf32.f32 "
        "{%0,%1,%2,%3}, {%4,%5,%6,%7}, {%8,%9}, {%0,%1,%2,%3};\n"
        : "+f"(c[0]), "+f"(c[1]), "+f"(c[2]), "+f"(c[3])
        : "r"(a0), "r"(a1), "r"(a2), "r"(a3), "r"(b0), "r"(b1));
}

// One-time W -> chunk-major fragment hi/lo split (layout unchanged from round 7)
extern "C" __global__ void prep_wfrag_kernel(const float* __restrict__ W) {
    int t    = blockIdx.x * 256 + threadIdx.x;   // 0..131071
    int lane = t & 31;
    int ksg  = (t >> 5) & 255;                   // global 8-col group
    int n8   = t >> 13;
    int r = n8 * 8 + (lane >> 2);
    int c = ksg * 8 + (lane & 3);
    float h0, l0, h1, l1;
    split_tf32(W[r * DIM + c],     h0, l0);
    split_tf32(W[r * DIM + c + 4], h1, l1);
    int chunk = ksg >> 2, ksl = ksg & 3;
    g_Wfrag[((chunk * 16 + n8) * 4 + ksl) * 32 + lane] = make_float4(h0, h1, l0, l1);
}

// Split prefetched x float4 (1 per thread) and store as A fragments.
// Thread owns row = tid>>3, quad q = tid&7 (cols q*4..q*4+3); ks = q>>1, half = q&1.
// Fragment float4 = {hi(c), lo(c), hi(c+4), lo(c+4)}; this thread writes the
// (half ? upper : lower) float2 of 4 consecutive tc slots.
__device__ __forceinline__ void store_a(char* abuf, float4 v, int tid) {
    int row = tid >> 3, q = tid & 7;
    int ks = q >> 1, half = q & 1;
    int rg = row >> 3, tr = row & 7;
    float h[4], l[4];
    split_tf32(v.x, h[0], l[0]); split_tf32(v.y, h[1], l[1]);
    split_tf32(v.z, h[2], l[2]); split_tf32(v.w, h[3], l[3]);
    char* base = abuf + (size_t)((rg * 4 + ks) * ABLK + ((tr + 2 * ks) & 7) * 4) * 16 + half * 8;
    #pragma unroll
    for (int j = 0; j < 4; j++)
        *(float2*)(base + j * 16) = make_float2(h[j], l[j]);
}

// Fused: tf32 3-product compensated GEMM (hh + hl + lh) + bias + softmax +
// group-limited top-4. 32 warps (8/SMSP), warp tile 32 rows x 16 experts,
// single register accumulator, TwoSum window-fold (every 4 chunks) into smem s.
extern "C" __global__ void __launch_bounds__(THREADS, 1)
gate_fused_kernel(const float* __restrict__ x, const float* __restrict__ bias,
                  float* __restrict__ out, int out_size, int Ttot)
{
    extern __shared__ char smem[];
    const uint32_t sb = smem_u32(smem);
    float* s_sm   = (float*)(smem + SOFF);   // TwoSum high parts: [16][THREADS]
    float* logits = (float*)smem;            // reused after GEMM: [128][LST]

    const int tid  = threadIdx.x;
    const int lane = tid & 31;
    const int warp = tid >> 5;
    const int wm   = warp & 3;       // 4 M groups of 32 rows
    const int wn   = warp >> 2;      // 8 N groups of 16 experts
    const long tokBase = (long)blockIdx.x * BM;

    // x pointer for this thread's staging slice (row = tid>>3, cols (tid&7)*4 ..)
    const float* xp = x + (tokBase + (tid >> 3)) * DIM + (tid & 7) * 4;

    float acc[2][2][4], c[2][2][4];
    #pragma unroll
    for (int i = 0; i < 2; i++)
        #pragma unroll
        for (int j = 0; j < 2; j++)
            #pragma unroll
            for (int k = 0; k < 4; k++) { acc[i][j][k] = 0.f; c[i][j][k] = 0.f; }
    #pragma unroll
    for (int j = 0; j < 16; j++) s_sm[j * THREADS + tid] = 0.f;

    // Prologue: stage chunk 0 (A synchronously, B via cp.async)
    {
        store_a(smem, *(const float4*)xp, tid);
        const float4* src = g_Wfrag;
        #pragma unroll
        for (int j = 0; j < 2; j++)
            cp_async16(sb + BOFF + (uint32_t)(j * THREADS + tid) * 16, src + j * THREADS + tid);
        CP_COMMIT();
        CP_WAIT0();
    }
    __syncthreads();

    for (int i = 0; i < NCHUNK; i++) {
        // Prefetch next chunk: x into registers, B via cp.async
        float4 xa;
        if (i + 1 < NCHUNK) {
            xa = *(const float4*)(xp + (i + 1) * KC);
            const float4* src = g_Wfrag + (size_t)(i + 1) * 2048;
            uint32_t bdst = sb + BOFF + (uint32_t)((i + 1) & 1) * BBUF_BYTES;
            #pragma unroll
            for (int j = 0; j < 2; j++)
                cp_async16(bdst + (uint32_t)(j * THREADS + tid) * 16, src + j * THREADS + tid);
            CP_COMMIT();
        }

        // Compute chunk i
        const float4* Asm = (const float4*)(smem + (i & 1) * ABUF_BYTES);
        const float4* Bsm = (const float4*)(smem + BOFF + (i & 1) * BBUF_BYTES);
        #pragma unroll
        for (int ks = 0; ks < 4; ks++) {
            float4 bf[2];
            #pragma unroll
            for (int nt = 0; nt < 2; nt++)
                bf[nt] = Bsm[((wn * 2 + nt) * 4 + ks) * 32 + lane];
            float4 af0[2], af1[2];
            const int li = (((lane >> 2) + 2 * ks) & 7) * 4 + (lane & 3);
            #pragma unroll
            for (int mt = 0; mt < 2; mt++) {
                int rg = wm * 4 + mt * 2;
                af0[mt] = Asm[(rg * 4 + ks) * ABLK + li];
                af1[mt] = Asm[((rg + 1) * 4 + ks) * ABLK + li];
            }
            #pragma unroll
            for (int nt = 0; nt < 2; nt++) {
                unsigned b0h = __float_as_uint(bf[nt].x), b1h = __float_as_uint(bf[nt].y);
                unsigned b0l = __float_as_uint(bf[nt].z), b1l = __float_as_uint(bf[nt].w);
                #pragma unroll
                for (int mt = 0; mt < 2; mt++) {
                    // A fragment layout: {hi(c), lo(c), hi(c+4), lo(c+4)}
                    unsigned a0h = __float_as_uint(af0[mt].x), a0l = __float_as_uint(af0[mt].y);
                    unsigned a2h = __float_as_uint(af0[mt].z), a2l = __float_as_uint(af0[mt].w);
                    unsigned a1h = __float_as_uint(af1[mt].x), a1l = __float_as_uint(af1[mt].y);
                    unsigned a3h = __float_as_uint(af1[mt].z), a3l = __float_as_uint(af1[mt].w);
                    mma_tf32(acc[mt][nt], a0h, a1h, a2h, a3h, b0h, b1h);  // hh
                    mma_tf32(acc[mt][nt], a0h, a1h, a2h, a3h, b0l, b1l);  // hl
                    mma_tf32(acc[mt][nt], a0l, a1l, a2l, a3l, b0h, b1h);  // lh
                }
            }
        }

        // Split + store the prefetched A register (after compute: LDG hidden)
        if (i + 1 < NCHUNK)
            store_a(smem + ((i + 1) & 1) * ABUF_BYTES, xa, tid);

        // Every 4 chunks (128 k-elems window): TwoSum-fold acc into (s_sm, c)
        if ((i & 3) == 3) {
            #pragma unroll
            for (int mt = 0; mt < 2; mt++)
                #pragma unroll
                for (int nt = 0; nt < 2; nt++)
                    #pragma unroll
                    for (int k = 0; k < 4; k++) {
                        int j = ((mt * 2 + nt) * 4 + k);
                        float p  = acc[mt][nt][k];
                        float sv = s_sm[j * THREADS + tid];
                        float z  = __fadd_rn(sv, p);
                        float t  = __fadd_rn(z, -sv);
                        float e1 = __fadd_rn(p, -t);
                        float t2 = __fadd_rn(z, -t);
                        float e2 = __fadd_rn(sv, -t2);
                        c[mt][nt][k] = __fadd_rn(c[mt][nt][k], __fadd_rn(e1, e2));
                        s_sm[j * THREADS + tid] = z;
                        acc[mt][nt][k] = 0.f;
                    }
        }
        CP_WAIT0();        // B[i+1] landed
        __syncthreads();   // all reads of buf[i&1] done; buf[(i+1)&1] ready
    }

    // Write logits (+bias) into smem for the fused routing epilogue
    #pragma unroll
    for (int mt = 0; mt < 2; mt++) {
        #pragma unroll
        for (int nt = 0; nt < 2; nt++) {
            int rowb = wm * 32 + mt * 16 + (lane >> 2);
            int colb = wn * 16 + nt * 8 + 2 * (lane & 3);
            float b0v = __ldg(bias + colb), b1v = __ldg(bias + colb + 1);
            #pragma unroll
            for (int half = 0; half < 2; half++) {
                int rw = rowb + half * 8;
                int j0 = ((mt * 2 + nt) * 4 + 2 * half);
                float s0 = s_sm[j0 * THREADS + tid];
                float s1 = s_sm[(j0 + 1) * THREADS + tid];
                float l0 = __fadd_rn(__fadd_rn(s0, c[mt][nt][2*half]),   b0v);
                float l1 = __fadd_rn(__fadd_rn(s1, c[mt][nt][2*half+1]), b1v);
                logits[rw * LST + colb]     = l0;
                logits[rw * LST + colb + 1] = l1;
            }
        }
    }
    __syncthreads();

    // Routing epilogue: 1 thread per token (identical to passing round-2..7 logic)
    if (tid < BM) {
        const float* row = logits + tid * LST;
        float v1[2], v2[2];
        #pragma unroll
        for (int g = 0; g < 2; g++) {
            float b1 = -INFINITY, b2 = -INFINITY;
            for (int j = 0; j < 64; j++) {
                float v = row[g * 64 + j];
                if (v > b1) { b2 = b1; b1 = v; } else if (v > b2) { b2 = v; }
            }
            v1[g] = b1; v2[g] = b2;
        }
        float m = fmaxf(v1[0], v1[1]);
        double s0 = exp((double)v1[0] - (double)m) + exp((double)v2[0] - (double)m);
        double s1 = exp((double)v1[1] - (double)m) + exp((double)v2[1] - (double)m);
        int gsel = (s1 > s0) ? 1 : 0;     // tie -> lower group index (matches lax.top_k)
        const float* grow = row + gsel * 64;
        unsigned long long used = 0ull;
        float vals[KSEL]; int ids[KSEL];
        #pragma unroll
        for (int p = 0; p < KSEL; p++) {  // sequential argmax: descending, ties -> lower idx
            float best = -INFINITY; int bi = 0;
            for (int j = 0; j < 64; j++) {
                if (!((used >> j) & 1ull)) {
                    float v = grow[j];
                    if (v > best) { best = v; bi = j; }
                }
            }
            used |= (1ull << bi);
            vals[p] = best; ids[p] = gsel * 64 + bi;
        }
        float e[KSEL], ssum = 0.f;
        #pragma unroll
        for (int p = 0; p < KSEL; p++) { e[p] = expf(vals[p] - m); ssum += e[p]; }
        ssum = fmaxf(ssum, 1e-9f);
        long tok = tokBase + tid;
        #pragma unroll
        for (int p = 0; p < KSEL; p++) out[tok * KSEL + p] = e[p] / ssum;
        if (out_size >= 2 * Ttot * KSEL) {   // [w ; idx] layout: indices as floats
            float* oi = out + (long)Ttot * KSEL;
            #pragma unroll
            for (int p = 0; p < KSEL; p++) oi[tok * KSEL + p] = (float)ids[p];
        }
    }
}

extern "C" void kernel_launch(void* const* d_in, const int* in_sizes, int n_in,
                              void* d_out, int out_size) {
    const float* x    = (const float*)d_in[0];
    const float* W    = (const float*)d_in[1];
    const float* bias = (const float*)d_in[2];
    float* out = (float*)d_out;

    int Ttot = in_sizes[0] / DIM;   // 65536
    int grid = Ttot / BM;           // 512

    cudaFuncSetAttribute((const void*)gate_fused_kernel,
                         cudaFuncAttributeMaxDynamicSharedMemorySize, SMEM_TOTAL);

    prep_wfrag_kernel<<<512, 256>>>(W);
    gate_fused_kernel<<<grid, THREADS, SMEM_TOTAL>>>(x, bias, out, out_size, Ttot);
}

// round 9
// speedup vs baseline: 1.1453x; 1.1453x over previous
#include <cuda_runtime.h>
#include <math.h>
#include <stdint.h>

#define DIM     2048
#define NE      128
#define KSEL    4
#define BM      128     // tokens per CTA
#define KC      32      // K elems per chunk (4 k-steps of 8)
#define NCHUNK  (DIM/KC)
#define THREADS 512
#define LST     129     // logits smem stride
#define ABLK    33      // padded float4 slots per (rowgroup, kstep) block

#define ABUF_BYTES (16 * 4 * ABLK * 16)   // 33792
#define BBUF_BYTES (2048 * 16)            // 32768
#define BOFF       (2 * ABUF_BYTES)       // 67584
#define SOFF       (BOFF + 2 * BBUF_BYTES)            // 133120
#define SMEM_TOTAL (SOFF + 32 * THREADS * 4)          // 198656

// Chunk-major fragment W (hi/lo split): g_Wfrag[((chunk*16 + n8)*4 + ksl)*32 + lane]
//   = {Whi[n8*8+tr][k], Whi[..][k+4], Wlo[..][k], Wlo[..][k+4]},
//   lane = tr*4+tc, k = chunk*32 + ksl*8 + tc
__device__ float4 g_Wfrag[NCHUNK * 2048];   // 2 MB

__device__ __forceinline__ uint32_t smem_u32(const void* p) {
    uint32_t a;
    asm("{ .reg .u64 t; cvta.to.shared.u64 t, %1; cvt.u32.u64 %0, t; }" : "=r"(a) : "l"(p));
    return a;
}
__device__ __forceinline__ void cp_async16(uint32_t dst, const void* src) {
    asm volatile("cp.async.cg.shared.global [%0], [%1], 16;" :: "r"(dst), "l"(src) : "memory");
}
#define CP_COMMIT() asm volatile("cp.async.commit_group;" ::: "memory")
#define CP_WAIT0()  asm volatile("cp.async.wait_group 0;" ::: "memory")

// Split fp32 into tf32 hi + tf32 lo (x = hi + lo + O(2^-33 x))
__device__ __forceinline__ void split_tf32(float v, float& hi, float& lo) {
    unsigned h, l;
    asm("cvt.rna.tf32.f32 %0, %1;" : "=r"(h) : "f"(v));
    hi = __uint_as_float(h);
    float r = v - hi;
    asm("cvt.rna.tf32.f32 %0, %1;" : "=r"(l) : "f"(r));
    lo = __uint_as_float(l);
}

__device__ __forceinline__ void mma_tf32(float c[4],
                                         unsigned a0, unsigned a1, unsigned a2, unsigned a3,
                                         unsigned b0, unsigned b1) {
    asm volatile(
        "mma.sync.aligned.m16n8k8.row.col.f32.tf32.tf32.f32 "
        "{%0,%1,%2,%3}, {%4,%5,%6,%7}, {%8,%9}, {%0,%1,%2,%3};\n"
        : "+f"(c[0]), "+f"(c[1]), "+f"(c[2]), "+f"(c[3])
        : "r"(a0), "r"(a1), "r"(a2), "r"(a3), "r"(b0), "r"(b1));
}

// One-time W -> chunk-major fragment hi/lo split
extern "C" __global__ void prep_wfrag_kernel(const float* __restrict__ W) {
    int t    = blockIdx.x * 256 + threadIdx.x;   // 0..131071
    int lane = t & 31;
    int ksg  = (t >> 5) & 255;                   // global 8-col group
    int n8   = t >> 13;
    int r = n8 * 8 + (lane >> 2);
    int c = ksg * 8 + (lane & 3);
    float h0, l0, h1, l1;
    split_tf32(W[r * DIM + c],     h0, l0);
    split_tf32(W[r * DIM + c + 4], h1, l1);
    int chunk = ksg >> 2, ksl = ksg & 3;
    g_Wfrag[((chunk * 16 + n8) * 4 + ksl) * 32 + lane] = make_float4(h0, h1, l0, l1);
}

// Split prefetched x registers and store fragment-major into A buffer.
__device__ __forceinline__ void store_a(char* abuf, float4 va, float4 vb, int tid) {
    int row = tid >> 2, ksl = tid & 3;
    int rg = row >> 3, tr = row & 7;
    float ha[4], la[4], hb[4], lb[4];
    split_tf32(va.x, ha[0], la[0]); split_tf32(va.y, ha[1], la[1]);
    split_tf32(va.z, ha[2], la[2]); split_tf32(va.w, ha[3], la[3]);
    split_tf32(vb.x, hb[0], lb[0]); split_tf32(vb.y, hb[1], lb[1]);
    split_tf32(vb.z, hb[2], lb[2]); split_tf32(vb.w, hb[3], lb[3]);
    float4* dst = (float4*)abuf + (size_t)((rg * 4 + ksl) * ABLK + ((tr + 2 * ksl) & 7) * 4);
    #pragma unroll
    for (int tc = 0; tc < 4; tc++)
        dst[tc] = make_float4(ha[tc], hb[tc], la[tc], lb[tc]);
}

// Fused: tf32 3-product compensated GEMM (hh + hl + lh) + bias + softmax +
// group-limited top-4. Round-7 config (512 thr, warp tile 32x32) with the mma
// stream restructured into 3 independent sweeps per k-step to break c->c RAW.
extern "C" __global__ void __launch_bounds__(THREADS, 1)
gate_fused_kernel(const float* __restrict__ x, const float* __restrict__ bias,
                  float* __restrict__ out, int out_size, int Ttot)
{
    extern __shared__ char smem[];
    const uint32_t sb = smem_u32(smem);
    float* s_sm   = (float*)(smem + SOFF);   // TwoSum high parts: [32][THREADS]
    float* logits = (float*)smem;            // reused after GEMM: [128][LST]

    const int tid  = threadIdx.x;
    const int lane = tid & 31;
    const int warp = tid >> 5;
    const int wm   = warp & 3;       // 4 M groups of 32 rows
    const int wn   = warp >> 2;      // 4 N groups of 32 experts
    const long tokBase = (long)blockIdx.x * BM;

    // x pointer for this thread's staging slice (row = tid>>2, cols ksl*8 ..)
    const float* xp = x + (tokBase + (tid >> 2)) * DIM + (tid & 3) * 8;

    float w[2][4][4], c[2][4][4];
    #pragma unroll
    for (int i = 0; i < 2; i++)
        #pragma unroll
        for (int j = 0; j < 4; j++)
            #pragma unroll
            for (int k = 0; k < 4; k++) { w[i][j][k] = 0.f; c[i][j][k] = 0.f; }
    #pragma unroll
    for (int j = 0; j < 32; j++) s_sm[j * THREADS + tid] = 0.f;

    // Prologue: stage chunk 0 (A synchronously, B via cp.async)
    {
        float4 va = *(const float4*)xp;
        float4 vb = *(const float4*)(xp + 4);
        store_a(smem, va, vb, tid);
        const float4* src = g_Wfrag;
        #pragma unroll
        for (int j = 0; j < 4; j++)
            cp_async16(sb + BOFF + (uint32_t)(j * THREADS + tid) * 16, src + j * THREADS + tid);
        CP_COMMIT();
        CP_WAIT0();
    }
    __syncthreads();

    for (int i = 0; i < NCHUNK; i++) {
        // Prefetch next chunk: x into registers (LDG latency hidden behind mma),
        // B via cp.async (completes before the bottom wait+sync).
        float4 xa, xb;
        if (i + 1 < NCHUNK) {
            xa = *(const float4*)(xp + (i + 1) * KC);
            xb = *(const float4*)(xp + (i + 1) * KC + 4);
            const float4* src = g_Wfrag + (size_t)(i + 1) * 2048;
            uint32_t bdst = sb + BOFF + (uint32_t)((i + 1) & 1) * BBUF_BYTES;
            #pragma unroll
            for (int j = 0; j < 4; j++)
                cp_async16(bdst + (uint32_t)(j * THREADS + tid) * 16, src + j * THREADS + tid);
            CP_COMMIT();
        }

        // Compute chunk i
        const float4* Asm = (const float4*)(smem + (i & 1) * ABUF_BYTES);
        const float4* Bsm = (const float4*)(smem + BOFF + (i & 1) * BBUF_BYTES);
        #pragma unroll
        for (int ks = 0; ks < 4; ks++) {
            float4 bf[4];
            #pragma unroll
            for (int nt = 0; nt < 4; nt++)
                bf[nt] = Bsm[((wn * 4 + nt) * 4 + ks) * 32 + lane];
            float4 af0[2], af1[2];
            const int li = (((lane >> 2) + 2 * ks) & 7) * 4 + (lane & 3);
            #pragma unroll
            for (int mt = 0; mt < 2; mt++) {
                int rg = wm * 4 + mt * 2;
                af0[mt] = Asm[(rg * 4 + ks) * ABLK + li];
                af1[mt] = Asm[((rg + 1) * 4 + ks) * ABLK + li];
            }
            // Sweep 1: hh -> w (8 independent accumulators, no RAW)
            #pragma unroll
            for (int nt = 0; nt < 4; nt++) {
                unsigned b0h = __float_as_uint(bf[nt].x), b1h = __float_as_uint(bf[nt].y);
                #pragma unroll
                for (int mt = 0; mt < 2; mt++)
                    mma_tf32(w[mt][nt],
                             __float_as_uint(af0[mt].x), __float_as_uint(af1[mt].x),
                             __float_as_uint(af0[mt].y), __float_as_uint(af1[mt].y),
                             b0h, b1h);
            }
            // Sweep 2: hl -> c (deps only on previous chunk's lh sweep, far away)
            #pragma unroll
            for (int nt = 0; nt < 4; nt++) {
                unsigned b0l = __float_as_uint(bf[nt].z), b1l = __float_as_uint(bf[nt].w);
                #pragma unroll
                for (int mt = 0; mt < 2; mt++)
                    mma_tf32(c[mt][nt],
                             __float_as_uint(af0[mt].x), __float_as_uint(af1[mt].x),
                             __float_as_uint(af0[mt].y), __float_as_uint(af1[mt].y),
                             b0l, b1l);
            }
            // Sweep 3: lh -> c (each 8 mmas after its hl partner)
            #pragma unroll
            for (int nt = 0; nt < 4; nt++) {
                unsigned b0h = __float_as_uint(bf[nt].x), b1h = __float_as_uint(bf[nt].y);
                #pragma unroll
                for (int mt = 0; mt < 2; mt++)
                    mma_tf32(c[mt][nt],
                             __float_as_uint(af0[mt].z), __float_as_uint(af1[mt].z),
                             __float_as_uint(af0[mt].w), __float_as_uint(af1[mt].w),
                             b0h, b1h);
            }
        }

        // Split + store the prefetched A registers (after compute: LDG hidden)
        if (i + 1 < NCHUNK)
            store_a(smem + ((i + 1) & 1) * ABUF_BYTES, xa, xb, tid);

        // Every 8 chunks (256 k-elems window): TwoSum-fold hh into (s_sm, c)
        if ((i & 7) == 7) {
            #pragma unroll
            for (int mt = 0; mt < 2; mt++)
                #pragma unroll
                for (int nt = 0; nt < 4; nt++)
                    #pragma unroll
                    for (int k = 0; k < 4; k++) {
                        int j = ((mt * 4 + nt) * 4 + k);
                        float p  = w[mt][nt][k];
                        float sv = s_sm[j * THREADS + tid];
                        float z  = __fadd_rn(sv, p);
                        float t  = __fadd_rn(z, -sv);
                        float e1 = __fadd_rn(p, -t);
                        float t2 = __fadd_rn(z, -t);
                        float e2 = __fadd_rn(sv, -t2);
                        c[mt][nt][k] = __fadd_rn(c[mt][nt][k], __fadd_rn(e1, e2));
                        s_sm[j * THREADS + tid] = z;
                        w[mt][nt][k] = 0.f;
                    }
        }
        CP_WAIT0();        // B[i+1] landed
        __syncthreads();   // all reads of buf[i&1] done; buf[(i+1)&1] ready
    }

    // Write logits (+bias) into smem for the fused routing epilogue
    #pragma unroll
    for (int mt = 0; mt < 2; mt++) {
        #pragma unroll
        for (int nt = 0; nt < 4; nt++) {
            int rowb = wm * 32 + mt * 16 + (lane >> 2);
            int colb = wn * 32 + nt * 8 + 2 * (lane & 3);
            float b0v = __ldg(bias + colb), b1v = __ldg(bias + colb + 1);
            #pragma unroll
            for (int half = 0; half < 2; half++) {
                int rw = rowb + half * 8;
                int j0 = ((mt * 4 + nt) * 4 + 2 * half);
                float s0 = s_sm[j0 * THREADS + tid];
                float s1 = s_sm[(j0 + 1) * THREADS + tid];
                float l0 = __fadd_rn(__fadd_rn(s0, c[mt][nt][2*half]),   b0v);
                float l1 = __fadd_rn(__fadd_rn(s1, c[mt][nt][2*half+1]), b1v);
                logits[rw * LST + colb]     = l0;
                logits[rw * LST + colb + 1] = l1;
            }
        }
    }
    __syncthreads();

    // Routing epilogue: 1 thread per token (identical to passing round-2..7 logic)
    if (tid < BM) {
        const float* row = logits + tid * LST;
        float v1[2], v2[2];
        #pragma unroll
        for (int g = 0; g < 2; g++) {
            float b1 = -INFINITY, b2 = -INFINITY;
            for (int j = 0; j < 64; j++) {
                float v = row[g * 64 + j];
                if (v > b1) { b2 = b1; b1 = v; } else if (v > b2) { b2 = v; }
            }
            v1[g] = b1; v2[g] = b2;
        }
        float m = fmaxf(v1[0], v1[1]);
        double s0 = exp((double)v1[0] - (double)m) + exp((double)v2[0] - (double)m);
        double s1 = exp((double)v1[1] - (double)m) + exp((double)v2[1] - (double)m);
        int gsel = (s1 > s0) ? 1 : 0;     // tie -> lower group index (matches lax.top_k)
        const float* grow = row + gsel * 64;
        unsigned long long used = 0ull;
        float vals[KSEL]; int ids[KSEL];
        #pragma unroll
        for (int p = 0; p < KSEL; p++) {  // sequential argmax: descending, ties -> lower idx
            float best = -INFINITY; int bi = 0;
            for (int j = 0; j < 64; j++) {
                if (!((used >> j) & 1ull)) {
                    float v = grow[j];
                    if (v > best) { best = v; bi = j; }
                }
            }
            used |= (1ull << bi);
            vals[p] = best; ids[p] = gsel * 64 + bi;
        }
        float e[KSEL], ssum = 0.f;
        #pragma unroll
        for (int p = 0; p < KSEL; p++) { e[p] = expf(vals[p] - m); ssum += e[p]; }
        ssum = fmaxf(ssum, 1e-9f);
        long tok = tokBase + tid;
        #pragma unroll
        for (int p = 0; p < KSEL; p++) out[tok * KSEL + p] = e[p] / ssum;
        if (out_size >= 2 * Ttot * KSEL) {   // [w ; idx] layout: indices as floats
            float* oi = out + (long)Ttot * KSEL;
            #pragma unroll
            for (int p = 0; p < KSEL; p++) oi[tok * KSEL + p] = (float)ids[p];
        }
    }
}

extern "C" void kernel_launch(void* const* d_in, const int* in_sizes, int n_in,
                              void* d_out, int out_size) {
    const float* x    = (const float*)d_in[0];
    const float* W    = (const float*)d_in[1];
    const float* bias = (const float*)d_in[2];
    float* out = (float*)d_out;

    int Ttot = in_sizes[0] / DIM;   // 65536
    int grid = Ttot / BM;           // 512

    cudaFuncSetAttribute((const void*)gate_fused_kernel,
                         cudaFuncAttributeMaxDynamicSharedMemorySize, SMEM_TOTAL);

    prep_wfrag_kernel<<<512, 256>>>(W);
    gate_fused_kernel<<<grid, THREADS, SMEM_TOTAL>>>(x, bias, out, out_size, Ttot);
}

// round 10
// speedup vs baseline: 1.2206x; 1.0657x over previous
#include <cuda_runtime.h>
#include <math.h>
#include <stdint.h>

#define DIM     2048
#define NE      128
#define KSEL    4
#define BM      128     // tokens per tile
#define KC      32      // K elems per chunk (4 k-steps of 8)
#define NCHALF  32      // chunks per half-K CTA
#define THREADS 512
#define LST     129     // logits smem stride
#define ABLK    33      // padded float4 slots per (rowgroup, kstep) block

#define ABUF_BYTES (16 * 4 * ABLK * 16)   // 33792
#define BBUF_BYTES (2048 * 16)            // 32768
#define BOFF       (2 * ABUF_BYTES)       // 67584
#define SOFF       (BOFF + 2 * BBUF_BYTES)            // 133120
#define SMEM_TOTAL (SOFF + 32 * THREADS * 4)          // 198656
#define RSMEM      (BM * LST * 4)                     // 66048 (route kernel)

// Chunk-major fragment W (hi/lo split), as in round 7/9.
__device__ float4 g_Wfrag[64 * 2048];            // 2 MB
// Partial logits: [tile][half][128 tok][128 experts], s+c combined fp32
__device__ float g_P[512 * 2 * BM * NE];         // 64 MB

__device__ __forceinline__ uint32_t smem_u32(const void* p) {
    uint32_t a;
    asm("{ .reg .u64 t; cvta.to.shared.u64 t, %1; cvt.u32.u64 %0, t; }" : "=r"(a) : "l"(p));
    return a;
}
__device__ __forceinline__ void cp_async16(uint32_t dst, const void* src) {
    asm volatile("cp.async.cg.shared.global [%0], [%1], 16;" :: "r"(dst), "l"(src) : "memory");
}
#define CP_COMMIT() asm volatile("cp.async.commit_group;" ::: "memory")
#define CP_WAIT0()  asm volatile("cp.async.wait_group 0;" ::: "memory")

__device__ __forceinline__ void split_tf32(float v, float& hi, float& lo) {
    unsigned h, l;
    asm("cvt.rna.tf32.f32 %0, %1;" : "=r"(h) : "f"(v));
    hi = __uint_as_float(h);
    float r = v - hi;
    asm("cvt.rna.tf32.f32 %0, %1;" : "=r"(l) : "f"(r));
    lo = __uint_as_float(l);
}

__device__ __forceinline__ void mma_tf32(float c[4],
                                         unsigned a0, unsigned a1, unsigned a2, unsigned a3,
                                         unsigned b0, unsigned b1) {
    asm volatile(
        "mma.sync.aligned.m16n8k8.row.col.f32.tf32.tf32.f32 "
        "{%0,%1,%2,%3}, {%4,%5,%6,%7}, {%8,%9}, {%0,%1,%2,%3};\n"
        : "+f"(c[0]), "+f"(c[1]), "+f"(c[2]), "+f"(c[3])
        : "r"(a0), "r"(a1), "r"(a2), "r"(a3), "r"(b0), "r"(b1));
}

// One-time W -> chunk-major fragment hi/lo split
extern "C" __global__ void prep_wfrag_kernel(const float* __restrict__ W) {
    int t    = blockIdx.x * 256 + threadIdx.x;   // 0..131071
    int lane = t & 31;
    int ksg  = (t >> 5) & 255;
    int n8   = t >> 13;
    int r = n8 * 8 + (lane >> 2);
    int c = ksg * 8 + (lane & 3);
    float h0, l0, h1, l1;
    split_tf32(W[r * DIM + c],     h0, l0);
    split_tf32(W[r * DIM + c + 4], h1, l1);
    int chunk = ksg >> 2, ksl = ksg & 3;
    g_Wfrag[((chunk * 16 + n8) * 4 + ksl) * 32 + lane] = make_float4(h0, h1, l0, l1);
}

// Split prefetched x registers and store fragment-major into A buffer.
__device__ __forceinline__ void store_a(char* abuf, float4 va, float4 vb, int tid) {
    int row = tid >> 2, ksl = tid & 3;
    int rg = row >> 3, tr = row & 7;
    float ha[4], la[4], hb[4], lb[4];
    split_tf32(va.x, ha[0], la[0]); split_tf32(va.y, ha[1], la[1]);
    split_tf32(va.z, ha[2], la[2]); split_tf32(va.w, ha[3], la[3]);
    split_tf32(vb.x, hb[0], lb[0]); split_tf32(vb.y, hb[1], lb[1]);
    split_tf32(vb.z, hb[2], lb[2]); split_tf32(vb.w, hb[3], lb[3]);
    float4* dst = (float4*)abuf + (size_t)((rg * 4 + ksl) * ABLK + ((tr + 2 * ksl) & 7) * 4);
    #pragma unroll
    for (int tc = 0; tc < 4; tc++)
        dst[tc] = make_float4(ha[tc], hb[tc], la[tc], lb[tc]);
}

// Kernel 1: tf32 3-product compensated GEMM over ONE K-half of one 128-token
// tile. Inner loop identical to the round-9 passing kernel. Writes s+c partial
// logits to g_P. grid = 1024 (tile, half) -> near-perfect wave balance (7/6.92).
extern "C" __global__ void __launch_bounds__(THREADS, 1)
gate_partial_kernel(const float* __restrict__ x)
{
    extern __shared__ char smem[];
    const uint32_t sb = smem_u32(smem);
    float* s_sm   = (float*)(smem + SOFF);   // TwoSum high parts: [32][THREADS]
    float* logits = (float*)smem;            // reused after GEMM: [128][LST]

    const int tid  = threadIdx.x;
    const int lane = tid & 31;
    const int warp = tid >> 5;
    const int wm   = warp & 3;       // 4 M groups of 32 rows
    const int wn   = warp >> 2;      // 4 N groups of 32 experts
    const int tile = blockIdx.x >> 1;
    const int half = blockIdx.x & 1;
    const long tokBase = (long)tile * BM;
    const int  g0   = half * NCHALF;         // first global chunk of this half

    const float* xp = x + (tokBase + (tid >> 2)) * DIM + g0 * KC + (tid & 3) * 8;

    float w[2][4][4], c[2][4][4];
    #pragma unroll
    for (int i = 0; i < 2; i++)
        #pragma unroll
        for (int j = 0; j < 4; j++)
            #pragma unroll
            for (int k = 0; k < 4; k++) { w[i][j][k] = 0.f; c[i][j][k] = 0.f; }
    #pragma unroll
    for (int j = 0; j < 32; j++) s_sm[j * THREADS + tid] = 0.f;

    // Prologue: stage chunk g0 (A synchronously, B via cp.async)
    {
        float4 va = *(const float4*)xp;
        float4 vb = *(const float4*)(xp + 4);
        store_a(smem, va, vb, tid);
        const float4* src = g_Wfrag + (size_t)g0 * 2048;
        #pragma unroll
        for (int j = 0; j < 4; j++)
            cp_async16(sb + BOFF + (uint32_t)(j * THREADS + tid) * 16, src + j * THREADS + tid);
        CP_COMMIT();
        CP_WAIT0();
    }
    __syncthreads();

    for (int i = 0; i < NCHALF; i++) {
        // Prefetch next chunk: x into registers, B via cp.async
        float4 xa, xb;
        if (i + 1 < NCHALF) {
            xa = *(const float4*)(xp + (i + 1) * KC);
            xb = *(const float4*)(xp + (i + 1) * KC + 4);
            const float4* src = g_Wfrag + (size_t)(g0 + i + 1) * 2048;
            uint32_t bdst = sb + BOFF + (uint32_t)((i + 1) & 1) * BBUF_BYTES;
            #pragma unroll
            for (int j = 0; j < 4; j++)
                cp_async16(bdst + (uint32_t)(j * THREADS + tid) * 16, src + j * THREADS + tid);
            CP_COMMIT();
        }

        // Compute chunk i
        const float4* Asm = (const float4*)(smem + (i & 1) * ABUF_BYTES);
        const float4* Bsm = (const float4*)(smem + BOFF + (i & 1) * BBUF_BYTES);
        #pragma unroll
        for (int ks = 0; ks < 4; ks++) {
            float4 bf[4];
            #pragma unroll
            for (int nt = 0; nt < 4; nt++)
                bf[nt] = Bsm[((wn * 4 + nt) * 4 + ks) * 32 + lane];
            float4 af0[2], af1[2];
            const int li = (((lane >> 2) + 2 * ks) & 7) * 4 + (lane & 3);
            #pragma unroll
            for (int mt = 0; mt < 2; mt++) {
                int rg = wm * 4 + mt * 2;
                af0[mt] = Asm[(rg * 4 + ks) * ABLK + li];
                af1[mt] = Asm[((rg + 1) * 4 + ks) * ABLK + li];
            }
            #pragma unroll
            for (int nt = 0; nt < 4; nt++) {
                unsigned b0h = __float_as_uint(bf[nt].x), b1h = __float_as_uint(bf[nt].y);
                unsigned b0l = __float_as_uint(bf[nt].z), b1l = __float_as_uint(bf[nt].w);
                #pragma unroll
                for (int mt = 0; mt < 2; mt++) {
                    unsigned a0h = __float_as_uint(af0[mt].x), a2h = __float_as_uint(af0[mt].y);
                    unsigned a0l = __float_as_uint(af0[mt].z), a2l = __float_as_uint(af0[mt].w);
                    unsigned a1h = __float_as_uint(af1[mt].x), a3h = __float_as_uint(af1[mt].y);
                    unsigned a1l = __float_as_uint(af1[mt].z), a3l = __float_as_uint(af1[mt].w);
                    mma_tf32(w[mt][nt], a0h, a1h, a2h, a3h, b0h, b1h);  // hh
                    mma_tf32(c[mt][nt], a0h, a1h, a2h, a3h, b0l, b1l);  // hl
                    mma_tf32(c[mt][nt], a0l, a1l, a2l, a3l, b0h, b1h);  // lh
                }
            }
        }

        // Split + store the prefetched A registers (after compute: LDG hidden)
        if (i + 1 < NCHALF)
            store_a(smem + ((i + 1) & 1) * ABUF_BYTES, xa, xb, tid);

        // Every 8 chunks (256 k-elems window): TwoSum-fold hh into (s_sm, c)
        if ((i & 7) == 7) {
            #pragma unroll
            for (int mt = 0; mt < 2; mt++)
                #pragma unroll
                for (int nt = 0; nt < 4; nt++)
                    #pragma unroll
                    for (int k = 0; k < 4; k++) {
                        int j = ((mt * 4 + nt) * 4 + k);
                        float p  = w[mt][nt][k];
                        float sv = s_sm[j * THREADS + tid];
                        float z  = __fadd_rn(sv, p);
                        float t  = __fadd_rn(z, -sv);
                        float e1 = __fadd_rn(p, -t);
                        float t2 = __fadd_rn(z, -t);
                        float e2 = __fadd_rn(sv, -t2);
                        c[mt][nt][k] = __fadd_rn(c[mt][nt][k], __fadd_rn(e1, e2));
                        s_sm[j * THREADS + tid] = z;
                        w[mt][nt][k] = 0.f;
                    }
        }
        CP_WAIT0();
        __syncthreads();
    }

    // Write partial logits (s + c) into smem, then coalesced copy to g_P
    #pragma unroll
    for (int mt = 0; mt < 2; mt++) {
        #pragma unroll
        for (int nt = 0; nt < 4; nt++) {
            int rowb = wm * 32 + mt * 16 + (lane >> 2);
            int colb = wn * 32 + nt * 8 + 2 * (lane & 3);
            #pragma unroll
            for (int hf = 0; hf < 2; hf++) {
                int rw = rowb + hf * 8;
                int j0 = ((mt * 4 + nt) * 4 + 2 * hf);
                float s0 = s_sm[j0 * THREADS + tid];
                float s1 = s_sm[(j0 + 1) * THREADS + tid];
                logits[rw * LST + colb]     = __fadd_rn(s0, c[mt][nt][2*hf]);
                logits[rw * LST + colb + 1] = __fadd_rn(s1, c[mt][nt][2*hf+1]);
            }
        }
    }
    __syncthreads();

    float* Pd = g_P + ((size_t)tile * 2 + half) * (BM * NE);
    #pragma unroll
    for (int j = 0; j < 32; j++) {
        int f = j * THREADS + tid;           // 0..16383, coalesced STG
        Pd[f] = logits[(f >> 7) * LST + (f & 127)];
    }
}

// Kernel 2: combine halves + bias, then the (unchanged) routing epilogue.
extern "C" __global__ void gate_route_kernel(const float* __restrict__ bias,
                                             float* __restrict__ out,
                                             int out_size, int Ttot)
{
    extern __shared__ float logits[];        // [128][LST]
    const int tid  = threadIdx.x;            // 128 threads = 1 per token
    const int tile = blockIdx.x;
    const long tokBase = (long)tile * BM;

    const float4* P0 = (const float4*)(g_P + ((size_t)tile * 2 + 0) * (BM * NE));
    const float4* P1 = (const float4*)(g_P + ((size_t)tile * 2 + 1) * (BM * NE));
    for (int j = 0; j < 32; j++) {
        int f4 = j * 128 + tid;              // float4 index, coalesced
        float4 a = P0[f4], b = P1[f4];
        int row = f4 >> 5, col = (f4 & 31) * 4;
        logits[row * LST + col]     = a.x + b.x + __ldg(bias + col);
        logits[row * LST + col + 1] = a.y + b.y + __ldg(bias + col + 1);
        logits[row * LST + col + 2] = a.z + b.z + __ldg(bias + col + 2);
        logits[row * LST + col + 3] = a.w + b.w + __ldg(bias + col + 3);
    }
    __syncthreads();

    const float* row = logits + tid * LST;
    float v1[2], v2[2];
    #pragma unroll
    for (int g = 0; g < 2; g++) {
        float b1 = -INFINITY, b2 = -INFINITY;
        for (int j = 0; j < 64; j++) {
            float v = row[g * 64 + j];
            if (v > b1) { b2 = b1; b1 = v; } else if (v > b2) { b2 = v; }
        }
        v1[g] = b1; v2[g] = b2;
    }
    float m = fmaxf(v1[0], v1[1]);
    double s0 = exp((double)v1[0] - (double)m) + exp((double)v2[0] - (double)m);
    double s1 = exp((double)v1[1] - (double)m) + exp((double)v2[1] - (double)m);
    int gsel = (s1 > s0) ? 1 : 0;            // tie -> lower group (matches lax.top_k)
    const float* grow = row + gsel * 64;
    unsigned long long used = 0ull;
    float vals[KSEL]; int ids[KSEL];
    #pragma unroll
    for (int p = 0; p < KSEL; p++) {         // sequential argmax, ties -> lower idx
        float best = -INFINITY; int bi = 0;
        for (int j = 0; j < 64; j++) {
            if (!((used >> j) & 1ull)) {
                float v = grow[j];
                if (v > best) { best = v; bi = j; }
            }
        }
        used |= (1ull << bi);
        vals[p] = best; ids[p] = gsel * 64 + bi;
    }
    float e[KSEL], ssum = 0.f;
    #pragma unroll
    for (int p = 0; p < KSEL; p++) { e[p] = expf(vals[p] - m); ssum += e[p]; }
    ssum = fmaxf(ssum, 1e-9f);
    long tok = tokBase + tid;
    #pragma unroll
    for (int p = 0; p < KSEL; p++) out[tok * KSEL + p] = e[p] / ssum;
    if (out_size >= 2 * Ttot * KSEL) {       // [w ; idx] layout: indices as floats
        float* oi = out + (long)Ttot * KSEL;
        #pragma unroll
        for (int p = 0; p < KSEL; p++) oi[tok * KSEL + p] = (float)ids[p];
    }
}

extern "C" void kernel_launch(void* const* d_in, const int* in_sizes, int n_in,
                              void* d_out, int out_size) {
    const float* x    = (const float*)d_in[0];
    const float* W    = (const float*)d_in[1];
    const float* bias = (const float*)d_in[2];
    float* out = (float*)d_out;

    int Ttot  = in_sizes[0] / DIM;     // 65536
    int tiles = Ttot / BM;             // 512

    cudaFuncSetAttribute((const void*)gate_partial_kernel,
                         cudaFuncAttributeMaxDynamicSharedMemorySize, SMEM_TOTAL);
    cudaFuncSetAttribute((const void*)gate_route_kernel,
                         cudaFuncAttributeMaxDynamicSharedMemorySize, RSMEM);

    prep_wfrag_kernel<<<512, 256>>>(W);
    gate_partial_kernel<<<tiles * 2, THREADS, SMEM_TOTAL>>>(x);
    gate_route_kernel<<<tiles, BM, RSMEM>>>(bias, out, out_size, Ttot);
}

// round 11
// speedup vs baseline: 1.2242x; 1.0030x over previous
#include <cuda_runtime.h>
#include <math.h>
#include <stdint.h>

#define DIM     2048
#define NE      128
#define KSEL    4
#define BM      128     // tokens per tile
#define KC      32      // K elems per chunk (4 k-steps of 8)
#define NCHALF  32      // chunks per half-K CTA
#define THREADS 512
#define LST     129     // logits smem stride
#define ABLK    33      // padded float4 slots per (rowgroup, kstep) block

#define ABUF_BYTES (16 * 4 * ABLK * 16)   // 33792
#define BBUF_BYTES (2048 * 16)            // 32768
#define BOFF       (2 * ABUF_BYTES)       // 67584
#define SOFF       (BOFF + 2 * BBUF_BYTES)            // 133120
#define SMEM_TOTAL (SOFF + 32 * THREADS * 4)          // 198656
#define RSMEM      (BM * LST * 4)                     // 66048 (route kernel)

// Chunk-major fragment W (hi/lo split), as in round 7/9.
__device__ float4 g_Wfrag[64 * 2048];            // 2 MB
// Partial logits: [tile][half][128 tok][128 experts], s+c combined fp32
__device__ float g_P[512 * 2 * BM * NE];         // 64 MB

__device__ __forceinline__ uint32_t smem_u32(const void* p) {
    uint32_t a;
    asm("{ .reg .u64 t; cvta.to.shared.u64 t, %1; cvt.u32.u64 %0, t; }" : "=r"(a) : "l"(p));
    return a;
}
__device__ __forceinline__ void cp_async16(uint32_t dst, const void* src) {
    asm volatile("cp.async.cg.shared.global [%0], [%1], 16;" :: "r"(dst), "l"(src) : "memory");
}
#define CP_COMMIT() asm volatile("cp.async.commit_group;" ::: "memory")
#define CP_WAIT0()  asm volatile("cp.async.wait_group 0;" ::: "memory")

__device__ __forceinline__ void split_tf32(float v, float& hi, float& lo) {
    unsigned h, l;
    asm("cvt.rna.tf32.f32 %0, %1;" : "=r"(h) : "f"(v));
    hi = __uint_as_float(h);
    float r = v - hi;
    asm("cvt.rna.tf32.f32 %0, %1;" : "=r"(l) : "f"(r));
    lo = __uint_as_float(l);
}

__device__ __forceinline__ void mma_tf32(float c[4],
                                         unsigned a0, unsigned a1, unsigned a2, unsigned a3,
                                         unsigned b0, unsigned b1) {
    asm volatile(
        "mma.sync.aligned.m16n8k8.row.col.f32.tf32.tf32.f32 "
        "{%0,%1,%2,%3}, {%4,%5,%6,%7}, {%8,%9}, {%0,%1,%2,%3};\n"
        : "+f"(c[0]), "+f"(c[1]), "+f"(c[2]), "+f"(c[3])
        : "r"(a0), "r"(a1), "r"(a2), "r"(a3), "r"(b0), "r"(b1));
}

// One-time W -> chunk-major fragment hi/lo split
extern "C" __global__ void prep_wfrag_kernel(const float* __restrict__ W) {
    int t    = blockIdx.x * 256 + threadIdx.x;   // 0..131071
    int lane = t & 31;
    int ksg  = (t >> 5) & 255;
    int n8   = t >> 13;
    int r = n8 * 8 + (lane >> 2);
    int c = ksg * 8 + (lane & 3);
    float h0, l0, h1, l1;
    split_tf32(W[r * DIM + c],     h0, l0);
    split_tf32(W[r * DIM + c + 4], h1, l1);
    int chunk = ksg >> 2, ksl = ksg & 3;
    g_Wfrag[((chunk * 16 + n8) * 4 + ksl) * 32 + lane] = make_float4(h0, h1, l0, l1);
}

// Split prefetched x registers and store fragment-major into A buffer.
__device__ __forceinline__ void store_a(char* abuf, float4 va, float4 vb, int tid) {
    int row = tid >> 2, ksl = tid & 3;
    int rg = row >> 3, tr = row & 7;
    float ha[4], la[4], hb[4], lb[4];
    split_tf32(va.x, ha[0], la[0]); split_tf32(va.y, ha[1], la[1]);
    split_tf32(va.z, ha[2], la[2]); split_tf32(va.w, ha[3], la[3]);
    split_tf32(vb.x, hb[0], lb[0]); split_tf32(vb.y, hb[1], lb[1]);
    split_tf32(vb.z, hb[2], lb[2]); split_tf32(vb.w, hb[3], lb[3]);
    float4* dst = (float4*)abuf + (size_t)((rg * 4 + ksl) * ABLK + ((tr + 2 * ksl) & 7) * 4);
    #pragma unroll
    for (int tc = 0; tc < 4; tc++)
        dst[tc] = make_float4(ha[tc], hb[tc], la[tc], lb[tc]);
}

// Kernel 1: tf32 3-product compensated GEMM over ONE K-half of one 128-token
// tile. Inner loop identical to the round-9 passing kernel. Writes s+c partial
// logits to g_P. grid = 1024 (tile, half) -> near-perfect wave balance (7/6.92).
extern "C" __global__ void __launch_bounds__(THREADS, 1)
gate_partial_kernel(const float* __restrict__ x)
{
    extern __shared__ char smem[];
    const uint32_t sb = smem_u32(smem);
    float* s_sm   = (float*)(smem + SOFF);   // TwoSum high parts: [32][THREADS]
    float* logits = (float*)smem;            // reused after GEMM: [128][LST]

    const int tid  = threadIdx.x;
    const int lane = tid & 31;
    const int warp = tid >> 5;
    const int wm   = warp & 3;       // 4 M groups of 32 rows
    const int wn   = warp >> 2;      // 4 N groups of 32 experts
    const int tile = blockIdx.x >> 1;
    const int half = blockIdx.x & 1;
    const long tokBase = (long)tile * BM;
    const int  g0   = half * NCHALF;         // first global chunk of this half

    const float* xp = x + (tokBase + (tid >> 2)) * DIM + g0 * KC + (tid & 3) * 8;

    float w[2][4][4], c[2][4][4];
    #pragma unroll
    for (int i = 0; i < 2; i++)
        #pragma unroll
        for (int j = 0; j < 4; j++)
            #pragma unroll
            for (int k = 0; k < 4; k++) { w[i][j][k] = 0.f; c[i][j][k] = 0.f; }
    #pragma unroll
    for (int j = 0; j < 32; j++) s_sm[j * THREADS + tid] = 0.f;

    // Prologue: stage chunk g0 (A synchronously, B via cp.async)
    {
        float4 va = *(const float4*)xp;
        float4 vb = *(const float4*)(xp + 4);
        store_a(smem, va, vb, tid);
        const float4* src = g_Wfrag + (size_t)g0 * 2048;
        #pragma unroll
        for (int j = 0; j < 4; j++)
            cp_async16(sb + BOFF + (uint32_t)(j * THREADS + tid) * 16, src + j * THREADS + tid);
        CP_COMMIT();
        CP_WAIT0();
    }
    __syncthreads();

    for (int i = 0; i < NCHALF; i++) {
        // Prefetch next chunk: x into registers, B via cp.async
        float4 xa, xb;
        if (i + 1 < NCHALF) {
            xa = *(const float4*)(xp + (i + 1) * KC);
            xb = *(const float4*)(xp + (i + 1) * KC + 4);
            const float4* src = g_Wfrag + (size_t)(g0 + i + 1) * 2048;
            uint32_t bdst = sb + BOFF + (uint32_t)((i + 1) & 1) * BBUF_BYTES;
            #pragma unroll
            for (int j = 0; j < 4; j++)
                cp_async16(bdst + (uint32_t)(j * THREADS + tid) * 16, src + j * THREADS + tid);
            CP_COMMIT();
        }

        // Compute chunk i
        const float4* Asm = (const float4*)(smem + (i & 1) * ABUF_BYTES);
        const float4* Bsm = (const float4*)(smem + BOFF + (i & 1) * BBUF_BYTES);
        #pragma unroll
        for (int ks = 0; ks < 4; ks++) {
            float4 bf[4];
            #pragma unroll
            for (int nt = 0; nt < 4; nt++)
                bf[nt] = Bsm[((wn * 4 + nt) * 4 + ks) * 32 + lane];
            float4 af0[2], af1[2];
            const int li = (((lane >> 2) + 2 * ks) & 7) * 4 + (lane & 3);
            #pragma unroll
            for (int mt = 0; mt < 2; mt++) {
                int rg = wm * 4 + mt * 2;
                af0[mt] = Asm[(rg * 4 + ks) * ABLK + li];
                af1[mt] = Asm[((rg + 1) * 4 + ks) * ABLK + li];
            }
            #pragma unroll
            for (int nt = 0; nt < 4; nt++) {
                unsigned b0h = __float_as_uint(bf[nt].x), b1h = __float_as_uint(bf[nt].y);
                unsigned b0l = __float_as_uint(bf[nt].z), b1l = __float_as_uint(bf[nt].w);
                #pragma unroll
                for (int mt = 0; mt < 2; mt++) {
                    unsigned a0h = __float_as_uint(af0[mt].x), a2h = __float_as_uint(af0[mt].y);
                    unsigned a0l = __float_as_uint(af0[mt].z), a2l = __float_as_uint(af0[mt].w);
                    unsigned a1h = __float_as_uint(af1[mt].x), a3h = __float_as_uint(af1[mt].y);
                    unsigned a1l = __float_as_uint(af1[mt].z), a3l = __float_as_uint(af1[mt].w);
                    mma_tf32(w[mt][nt], a0h, a1h, a2h, a3h, b0h, b1h);  // hh
                    mma_tf32(c[mt][nt], a0h, a1h, a2h, a3h, b0l, b1l);  // hl
                    mma_tf32(c[mt][nt], a0l, a1l, a2l, a3l, b0h, b1h);  // lh
                }
            }
        }

        // Split + store the prefetched A registers (after compute: LDG hidden)
        if (i + 1 < NCHALF)
            store_a(smem + ((i + 1) & 1) * ABUF_BYTES, xa, xb, tid);

        // Every 8 chunks (256 k-elems window): TwoSum-fold hh into (s_sm, c)
        if ((i & 7) == 7) {
            #pragma unroll
            for (int mt = 0; mt < 2; mt++)
                #pragma unroll
                for (int nt = 0; nt < 4; nt++)
                    #pragma unroll
                    for (int k = 0; k < 4; k++) {
                        int j = ((mt * 4 + nt) * 4 + k);
                        float p  = w[mt][nt][k];
                        float sv = s_sm[j * THREADS + tid];
                        float z  = __fadd_rn(sv, p);
                        float t  = __fadd_rn(z, -sv);
                        float e1 = __fadd_rn(p, -t);
                        float t2 = __fadd_rn(z, -t);
                        float e2 = __fadd_rn(sv, -t2);
                        c[mt][nt][k] = __fadd_rn(c[mt][nt][k], __fadd_rn(e1, e2));
                        s_sm[j * THREADS + tid] = z;
                        w[mt][nt][k] = 0.f;
                    }
        }
        CP_WAIT0();
        __syncthreads();
    }

    // Write partial logits (s + c) into smem, then coalesced copy to g_P
    #pragma unroll
    for (int mt = 0; mt < 2; mt++) {
        #pragma unroll
        for (int nt = 0; nt < 4; nt++) {
            int rowb = wm * 32 + mt * 16 + (lane >> 2);
            int colb = wn * 32 + nt * 8 + 2 * (lane & 3);
            #pragma unroll
            for (int hf = 0; hf < 2; hf++) {
                int rw = rowb + hf * 8;
                int j0 = ((mt * 4 + nt) * 4 + 2 * hf);
                float s0 = s_sm[j0 * THREADS + tid];
                float s1 = s_sm[(j0 + 1) * THREADS + tid];
                logits[rw * LST + colb]     = __fadd_rn(s0, c[mt][nt][2*hf]);
                logits[rw * LST + colb + 1] = __fadd_rn(s1, c[mt][nt][2*hf+1]);
            }
        }
    }
    __syncthreads();

    float* Pd = g_P + ((size_t)tile * 2 + half) * (BM * NE);
    #pragma unroll
    for (int j = 0; j < 32; j++) {
        int f = j * THREADS + tid;           // 0..16383, coalesced STG
        Pd[f] = logits[(f >> 7) * LST + (f & 127)];
    }
}

// Kernel 2: combine halves + bias, then the (unchanged) routing epilogue.
extern "C" __global__ void gate_route_kernel(const float* __restrict__ bias,
                                             float* __restrict__ out,
                                             int out_size, int Ttot)
{
    extern __shared__ float logits[];        // [128][LST]
    const int tid  = threadIdx.x;            // 128 threads = 1 per token
    const int tile = blockIdx.x;
    const long tokBase = (long)tile * BM;

    const float4* P0 = (const float4*)(g_P + ((size_t)tile * 2 + 0) * (BM * NE));
    const float4* P1 = (const float4*)(g_P + ((size_t)tile * 2 + 1) * (BM * NE));
    for (int j = 0; j < 32; j++) {
        int f4 = j * 128 + tid;              // float4 index, coalesced
        float4 a = P0[f4], b = P1[f4];
        int row = f4 >> 5, col = (f4 & 31) * 4;
        logits[row * LST + col]     = a.x + b.x + __ldg(bias + col);
        logits[row * LST + col + 1] = a.y + b.y + __ldg(bias + col + 1);
        logits[row * LST + col + 2] = a.z + b.z + __ldg(bias + col + 2);
        logits[row * LST + col + 3] = a.w + b.w + __ldg(bias + col + 3);
    }
    __syncthreads();

    const float* row = logits + tid * LST;
    float v1[2], v2[2];
    #pragma unroll
    for (int g = 0; g < 2; g++) {
        float b1 = -INFINITY, b2 = -INFINITY;
        for (int j = 0; j < 64; j++) {
            float v = row[g * 64 + j];
            if (v > b1) { b2 = b1; b1 = v; } else if (v > b2) { b2 = v; }
        }
        v1[g] = b1; v2[g] = b2;
    }
    float m = fmaxf(v1[0], v1[1]);
    double s0 = exp((double)v1[0] - (double)m) + exp((double)v2[0] - (double)m);
    double s1 = exp((double)v1[1] - (double)m) + exp((double)v2[1] - (double)m);
    int gsel = (s1 > s0) ? 1 : 0;            // tie -> lower group (matches lax.top_k)
    const float* grow = row + gsel * 64;
    unsigned long long used = 0ull;
    float vals[KSEL]; int ids[KSEL];
    #pragma unroll
    for (int p = 0; p < KSEL; p++) {         // sequential argmax, ties -> lower idx
        float best = -INFINITY; int bi = 0;
        for (int j = 0; j < 64; j++) {
            if (!((used >> j) & 1ull)) {
                float v = grow[j];
                if (v > best) { best = v; bi = j; }
            }
        }
        used |= (1ull << bi);
        vals[p] = best; ids[p] = gsel * 64 + bi;
    }
    float e[KSEL], ssum = 0.f;
    #pragma unroll
    for (int p = 0; p < KSEL; p++) { e[p] = expf(vals[p] - m); ssum += e[p]; }
    ssum = fmaxf(ssum, 1e-9f);
    long tok = tokBase + tid;
    #pragma unroll
    for (int p = 0; p < KSEL; p++) out[tok * KSEL + p] = e[p] / ssum;
    if (out_size >= 2 * Ttot * KSEL) {       // [w ; idx] layout: indices as floats
        float* oi = out + (long)Ttot * KSEL;
        #pragma unroll
        for (int p = 0; p < KSEL; p++) oi[tok * KSEL + p] = (float)ids[p];
    }
}

extern "C" void kernel_launch(void* const* d_in, const int* in_sizes, int n_in,
                              void* d_out, int out_size) {
    const float* x    = (const float*)d_in[0];
    const float* W    = (const float*)d_in[1];
    const float* bias = (const float*)d_in[2];
    float* out = (float*)d_out;

    int Ttot  = in_sizes[0] / DIM;     // 65536
    int tiles = Ttot / BM;             // 512

    cudaFuncSetAttribute((const void*)gate_partial_kernel,
                         cudaFuncAttributeMaxDynamicSharedMemorySize, SMEM_TOTAL);
    cudaFuncSetAttribute((const void*)gate_route_kernel,
                         cudaFuncAttributeMaxDynamicSharedMemorySize, RSMEM);

    prep_wfrag_kernel<<<512, 256>>>(W);
    gate_partial_kernel<<<tiles * 2, THREADS, SMEM_TOTAL>>>(x);
    gate_route_kernel<<<tiles, BM, RSMEM>>>(bias, out, out_size, Ttot);
}